// round 6
// baseline (speedup 1.0000x reference)
#include <cuda_runtime.h>
#include <math_constants.h>

// Problem constants
#define NSL     24
#define BB      16
#define CCH     512
#define HWN     256          // H*W
#define FEAT_IN 1024
#define CLASSES 3
#define CG      8            // c-values per CTA (one per warp)
#define CTAS_PER_B (CCH / CG)       // 64
#define GRID    (BB * CTAS_PER_B)   // 1024
#define SLICE_STRIDE ((size_t)BB * CCH * HWN)   // floats per slice

// Persistent scratch (zero at module load; each launch restores it to zero).
__device__ float        g_acc[BB * CLASSES];
__device__ unsigned int g_count[BB];

// Fused kernel: 1024 CTAs x 256 threads, one wave. Warp owns channel c.
// Slices processed in 6 groups of 4 with a batched butterfly reduction:
// 6 shuffles reduce 4 segment sums simultaneously (vs 5 shuffles per segment),
// deferring the slice-max to one 5-step max butterfly at the end.
__global__ __launch_bounds__(256, 7) void fused_kernel(
    const float* __restrict__ feat_f_map,
    const float* __restrict__ oct_maps,
    const float* __restrict__ head_w,
    const float* __restrict__ head_b,
    float* __restrict__ out)
{
    const int gid  = blockIdx.x;          // 0..1023
    const int b    = gid >> 6;            // / 64
    const int cg   = gid & 63;            // % 64
    const int warp = threadIdx.x >> 5;    // 0..7
    const int lane = threadIdx.x & 31;
    const int c    = cg * CG + warp;      // this warp's channel

    const size_t bc_off = ((size_t)(b * CCH + c)) << 8;   // *HWN

    // 24 oct slices in 6 groups of 4 -> per-lane segment sums -> deferred max
    float vmax = -CUDART_INF_F;
    #pragma unroll 2
    for (int g = 0; g < 6; g++) {
        float p[4];
        #pragma unroll
        for (int j = 0; j < 4; j++) {
            const int s = g * 4 + j;
            const float4* ptr = (const float4*)
                (oct_maps + (size_t)s * SLICE_STRIDE + bc_off);
            float4 v0 = ptr[lane], v1 = ptr[lane + 32];
            p[j] = ((v0.x + v0.y) + (v0.z + v0.w))
                 + ((v1.x + v1.y) + (v1.z + v1.w));
        }
        // Batched butterfly: reduce 4 segment sums with 6 shuffles.
        // off16: halve 4->2 (segment pair chosen by lane bit4)
        float k0 = (lane & 16) ? p[2] : p[0];
        float r0 = __shfl_xor_sync(0xffffffffu, (lane & 16) ? p[0] : p[2], 16);
        float q0 = k0 + r0;
        float k1 = (lane & 16) ? p[3] : p[1];
        float r1 = __shfl_xor_sync(0xffffffffu, (lane & 16) ? p[1] : p[3], 16);
        float q1 = k1 + r1;
        // off8: halve 2->1 (segment chosen by lane bit3)
        float k2 = (lane & 8) ? q1 : q0;
        float r2 = __shfl_xor_sync(0xffffffffu, (lane & 8) ? q0 : q1, 8);
        float t  = k2 + r2;
        // off4/2/1: partners now hold the same segment -> plain sums
        t += __shfl_xor_sync(0xffffffffu, t, 4);
        t += __shfl_xor_sync(0xffffffffu, t, 2);
        t += __shfl_xor_sync(0xffffffffu, t, 1);
        // lane now holds the complete sum of ONE of the 4 segments
        vmax = fmaxf(vmax, t);
    }
    // Max butterfly: every lane has maxed 6 of the 24 segments; combine.
    #pragma unroll
    for (int off = 16; off; off >>= 1)
        vmax = fmaxf(vmax, __shfl_xor_sync(0xffffffffu, vmax, off));

    // feat_f segment: contiguous 1KB, classic reduce
    float sff;
    {
        const float4* p4 = (const float4*)(feat_f_map + bc_off);
        float4 v0 = p4[lane], v1 = p4[lane + 32];
        float s = ((v0.x + v0.y) + (v0.z + v0.w))
                + ((v1.x + v1.y) + (v1.z + v1.w));
        #pragma unroll
        for (int off = 16; off; off >>= 1)
            s += __shfl_xor_sync(0xffffffffu, s, off);
        sff = s;
    }

    // Head contribution for this c (lane 0 of each warp) -> shared acc
    __shared__ float    s_acc[CLASSES];
    __shared__ unsigned s_ticket;
    if (threadIdx.x < CLASSES) s_acc[threadIdx.x] = 0.f;
    __syncthreads();

    if (lane == 0) {
        const float inv = 1.0f / (float)HWN;
        const float ff = sff  * inv;      // feat_f[b][c]
        const float fo = vmax * inv;      // feat_o[b][c] = max_s mean_HW
        #pragma unroll
        for (int cl = 0; cl < CLASSES; cl++) {
            const float* w = head_w + cl * FEAT_IN;
            atomicAdd(&s_acc[cl], ff * w[c] + fo * w[CCH + c]);
        }
    }
    __syncthreads();

    if (threadIdx.x < CLASSES)
        atomicAdd(&g_acc[b * CLASSES + threadIdx.x], s_acc[threadIdx.x]);

    // Per-b completion ticket (release: fence before counter increment)
    __threadfence();
    if (threadIdx.x == 0)
        s_ticket = atomicAdd(&g_count[b], 1u);
    __syncthreads();

    if (s_ticket == CTAS_PER_B - 1) {
        // Last CTA of this b: finalize its 3 outputs, restore scratch state.
        if (threadIdx.x < CLASSES) {
            float v = atomicExch(&g_acc[b * CLASSES + threadIdx.x], 0.f);
            out[b * CLASSES + threadIdx.x] = v + head_b[threadIdx.x];
        }
        if (threadIdx.x == 0)
            atomicExch(&g_count[b], 0u);
    }
}

extern "C" void kernel_launch(void* const* d_in, const int* in_sizes, int n_in,
                              void* d_out, int out_size)
{
    const float* feat_f_map = (const float*)d_in[0];  // (16,512,16,16)
    const float* oct_maps   = (const float*)d_in[1];  // (24,16,512,16,16)
    const float* head_w     = (const float*)d_in[2];  // (3,1024)
    const float* head_b     = (const float*)d_in[3];  // (3,)
    float* out = (float*)d_out;                        // (16,3)

    fused_kernel<<<GRID, 256>>>(feat_f_map, oct_maps, head_w, head_b, out);
}

// round 7
// speedup vs baseline: 1.0077x; 1.0077x over previous
#include <cuda_runtime.h>
#include <math_constants.h>

// Problem constants
#define NSL     24
#define BB      16
#define CCH     512
#define HWN     256          // H*W
#define FEAT_IN 1024
#define CLASSES 3
#define CG      8            // c-values per CTA (one per warp)
#define CTAS_PER_B (CCH / CG)       // 64
#define GRID    (BB * CTAS_PER_B)   // 1024
#define SLICE_STRIDE ((size_t)BB * CCH * HWN)   // floats per slice (2M)

// Persistent scratch (zero at module load; each launch restores it to zero).
__device__ float        g_acc[BB * CLASSES];
__device__ unsigned int g_count[BB];

// Fused kernel: 1024 CTAs x 256 threads, one wave. Warp owns channel c.
// Each CTA starts its slice loop at a rotated offset (gid % 24) so the
// grid's instantaneous DRAM footprint spans all 24 slices (192MB) instead
// of one hot 8MB slice window — decorrelating channel/row-buffer pressure.
// Max over slices is order-independent, so the result is bit-identical.
__global__ __launch_bounds__(256, 7) void fused_kernel(
    const float* __restrict__ feat_f_map,
    const float* __restrict__ oct_maps,
    const float* __restrict__ head_w,
    const float* __restrict__ head_b,
    float* __restrict__ out)
{
    const int gid  = blockIdx.x;          // 0..1023
    const int b    = gid >> 6;            // / 64
    const int cg   = gid & 63;            // % 64
    const int warp = threadIdx.x >> 5;    // 0..7
    const int lane = threadIdx.x & 31;
    const int c    = cg * CG + warp;      // this warp's channel
    const int s0   = gid % NSL;           // slice rotation offset

    const size_t bc_off = ((size_t)(b * CCH + c)) << 8;   // *HWN

    // feat_f segment: contiguous 1KB
    float sff;
    {
        const float4* p4 = (const float4*)(feat_f_map + bc_off);
        float4 v0 = p4[lane], v1 = p4[lane + 32];
        float s = ((v0.x + v0.y) + (v0.z + v0.w))
                + ((v1.x + v1.y) + (v1.z + v1.w));
        #pragma unroll
        for (int off = 16; off; off >>= 1)
            s += __shfl_xor_sync(0xffffffffu, s, off);
        sff = s;
    }

    // 24 oct slices (rotated order): max over slice sums
    float vmax = -CUDART_INF_F;
    #pragma unroll 3
    for (int i = 0; i < NSL; i++) {
        int s = s0 + i; if (s >= NSL) s -= NSL;
        const float4* p = (const float4*)
            (oct_maps + (size_t)s * SLICE_STRIDE + bc_off);
        float4 v0 = p[lane], v1 = p[lane + 32];
        float t = ((v0.x + v0.y) + (v0.z + v0.w))
                + ((v1.x + v1.y) + (v1.z + v1.w));
        #pragma unroll
        for (int off = 16; off; off >>= 1)
            t += __shfl_xor_sync(0xffffffffu, t, off);
        vmax = fmaxf(vmax, t);
    }

    // Head contribution for this c (lane 0 of each warp) -> shared acc
    __shared__ float    s_acc[CLASSES];
    __shared__ unsigned s_ticket;
    if (threadIdx.x < CLASSES) s_acc[threadIdx.x] = 0.f;
    __syncthreads();

    if (lane == 0) {
        const float inv = 1.0f / (float)HWN;
        const float ff = sff  * inv;      // feat_f[b][c]
        const float fo = vmax * inv;      // feat_o[b][c] = max_s mean_HW
        #pragma unroll
        for (int cl = 0; cl < CLASSES; cl++) {
            const float* w = head_w + cl * FEAT_IN;
            atomicAdd(&s_acc[cl], ff * w[c] + fo * w[CCH + c]);
        }
    }
    __syncthreads();

    if (threadIdx.x < CLASSES)
        atomicAdd(&g_acc[b * CLASSES + threadIdx.x], s_acc[threadIdx.x]);

    // Per-b completion ticket (release: fence before counter increment)
    __threadfence();
    if (threadIdx.x == 0)
        s_ticket = atomicAdd(&g_count[b], 1u);
    __syncthreads();

    if (s_ticket == CTAS_PER_B - 1) {
        // Last CTA of this b: finalize its 3 outputs, restore scratch state.
        if (threadIdx.x < CLASSES) {
            float v = atomicExch(&g_acc[b * CLASSES + threadIdx.x], 0.f);
            out[b * CLASSES + threadIdx.x] = v + head_b[threadIdx.x];
        }
        if (threadIdx.x == 0)
            atomicExch(&g_count[b], 0u);
    }
}

extern "C" void kernel_launch(void* const* d_in, const int* in_sizes, int n_in,
                              void* d_out, int out_size)
{
    const float* feat_f_map = (const float*)d_in[0];  // (16,512,16,16)
    const float* oct_maps   = (const float*)d_in[1];  // (24,16,512,16,16)
    const float* head_w     = (const float*)d_in[2];  // (3,1024)
    const float* head_b     = (const float*)d_in[3];  // (3,)
    float* out = (float*)d_out;                        // (16,3)

    fused_kernel<<<GRID, 256>>>(feat_f_map, oct_maps, head_w, head_b, out);
}